// round 11
// baseline (speedup 1.0000x reference)
#include <cuda_runtime.h>
#include <cuda_fp16.h>
#include <cstdint>

// Problem dims
#define LDIM 128
#define BDIM 2048
#define DDIM 300
#define HDIM 60

// Fused-kernel layout: one CTA = one b, one 30-row l-segment
#define KC     32
#define NCH    10
#define SRS2   312         // S smem row stride (halfs)
#define QST    66          // q smem row stride (floats)
#define NTHR   256
#define ROWS   32          // smem rows: global l0-1 .. l0+30 (2 m16 tiles)
#define OUTR   30
#define NSEG   5
#define KSTEPS 19          // ceil(300/16)

// Pre-packed B fragments (fp16 pairs), 38.9 KB, L1/L2-resident
__device__ uint2 g_bpackh[KSTEPS * 256];

__device__ __forceinline__ void mma_f16(float* c, uint32_t a0, uint32_t a1,
                                        uint32_t a2, uint32_t a3,
                                        uint32_t b0, uint32_t b1) {
    asm volatile(
        "mma.sync.aligned.m16n8k16.row.col.f32.f16.f16.f32 "
        "{%0,%1,%2,%3}, {%4,%5,%6,%7}, {%8,%9}, {%0,%1,%2,%3};"
        : "+f"(c[0]), "+f"(c[1]), "+f"(c[2]), "+f"(c[3])
        : "r"(a0), "r"(a1), "r"(a2), "r"(a3), "r"(b0), "r"(b1));
}
__device__ __forceinline__ float4 lds_h4(const __half* p) {
    uint2 u = *reinterpret_cast<const uint2*>(p);
    __half2 a = *reinterpret_cast<__half2*>(&u.x);
    __half2 b = *reinterpret_cast<__half2*>(&u.y);
    float2 fa = __half22float2(a), fb = __half22float2(b);
    return make_float4(fa.x, fa.y, fb.x, fb.y);
}

// ---------------------------------------------------------------------------
// Kernel 0 (one-shot, tiny): pack B fragments, fp16.
// Entry (ks, n, lane): b0 = (P[k][h], P[k+1][h]), b1 = (P[k+8][h], P[k+9][h])
// with k = 16*ks + 2*tig, h = 8*n + g; zero outside K=300 / H=60.
// ---------------------------------------------------------------------------
__global__ void k_packB(const float* __restrict__ P) {
    const int e = blockIdx.x * 256 + threadIdx.x;
    if (e >= KSTEPS * 256) return;
    const int ks = e >> 8;
    const int n  = (e >> 5) & 7;
    const int ln = e & 31;
    const int tg = ln & 3, g = ln >> 2;
    const int k  = ks * 16 + 2 * tg;
    const int h  = 8 * n + g;
    float v[4] = {0.f, 0.f, 0.f, 0.f};
    if (h < HDIM) {
        if (k     < DDIM) v[0] = P[(size_t)(k)     * HDIM + h];
        if (k + 1 < DDIM) v[1] = P[(size_t)(k + 1) * HDIM + h];
        if (k + 8 < DDIM) v[2] = P[(size_t)(k + 8) * HDIM + h];
        if (k + 9 < DDIM) v[3] = P[(size_t)(k + 9) * HDIM + h];
    }
    __half2 b0 = __floats2half2_rn(v[0], v[1]);
    __half2 b1 = __floats2half2_rn(v[2], v[3]);
    uint2 u;
    u.x = *reinterpret_cast<uint32_t*>(&b0);
    u.y = *reinterpret_cast<uint32_t*>(&b1);
    g_bpackh[e] = u;
}

// ---------------------------------------------------------------------------
// Fused kernel: blockIdx -> (b = blk/NSEG, seg), l0 = 30*seg.
//  1) stage S rows (fp16, invalid rows = zeros), one barrier
//  2) MMA: warps 0-3, warp = (tile t, n-half nh): A redundancy 2x (was 4x)
//  3) norms / neighbor-dots / masked softmax
//  4) combine via REGISTER ROTATION: thread owns (col j, 10-long l-chunk),
//     each smem element read ~1.2x (was 3x)
// Smem 28.9 KB -> 5 CTAs/SM.
// ---------------------------------------------------------------------------
__global__ __launch_bounds__(NTHR, 5) void k_fused(const float* __restrict__ S,
                                                   const int* __restrict__ size,
                                                   float* __restrict__ out) {
    extern __shared__ char smraw[];
    __half* s_h  = reinterpret_cast<__half*>(smraw);                   // [ROWS][SRS2]
    float*  q_sm = reinterpret_cast<float*>(smraw + ROWS * SRS2 * 2);  // [ROWS][QST]
    float*  nrm  = q_sm + ROWS * QST;                                  // [ROWS]
    float*  crs  = nrm + ROWS;                                         // [ROWS]
    float2* wsm  = reinterpret_cast<float2*>(crs + ROWS);              // [OUTR]
    const uint32_t* sh32 = reinterpret_cast<const uint32_t*>(s_h);

    const int tid  = threadIdx.x;
    const int w    = tid >> 5;
    const int lane = tid & 31;
    const int g    = lane >> 2;
    const int tig  = lane & 3;
    const int blk  = blockIdx.x;
    const int b    = blk / NSEG;
    const int l0   = (blk - b * NSEG) * OUTR;

    // ---- stage all S rows: thread = (row = tid>>3, kq4 = tid&7) ----
    {
        const int row  = tid >> 3;
        const int kq4  = tid & 7;
        const int grow = l0 - 1 + row;
        const bool gv  = (grow >= 0 && grow < LDIM);
        const float* base = S + ((size_t)(gv ? grow : 0) * BDIM + b) * DDIM;
        __half* drow = s_h + row * SRS2;
#pragma unroll
        for (int c = 0; c < NCH; ++c) {
            const int k0 = c * KC + kq4 * 4;
            if (k0 >= SRS2) break;
            float4 v = make_float4(0.f, 0.f, 0.f, 0.f);
            if (gv && k0 + 4 <= DDIM) v = *reinterpret_cast<const float4*>(base + k0);
            __half2 h01 = __floats2half2_rn(v.x, v.y);
            __half2 h23 = __floats2half2_rn(v.z, v.w);
            uint2 u;
            u.x = *reinterpret_cast<uint32_t*>(&h01);
            u.y = *reinterpret_cast<uint32_t*>(&h23);
            *reinterpret_cast<uint2*>(drow + k0) = u;
        }
    }
    __syncthreads();

    // ---- MMA: warps 0-3; warp = (tile t = w>>1, n-half nh = w&1) ----
    if (w < 4) {
        float acc[4][4];
#pragma unroll
        for (int n = 0; n < 4; ++n)
#pragma unroll
            for (int i = 0; i < 4; ++i) acc[n][i] = 0.f;

        const int t     = w >> 1;
        const int nh    = w & 1;
        const int rbase = 16 * t + g;

#pragma unroll
        for (int ks = 0; ks < KSTEPS; ++ks) {
            const int base0 = rbase * 156 + ks * 8 + tig;   // u32 view, stride 156
            const uint32_t a0 = sh32[base0];
            const uint32_t a1 = sh32[base0 + 8 * 156];
            const uint32_t a2 = sh32[base0 + 4];
            const uint32_t a3 = sh32[base0 + 8 * 156 + 4];
#pragma unroll
            for (int nn = 0; nn < 4; ++nn) {
                const uint2 bb = __ldg(&g_bpackh[(ks * 8 + 4 * nh + nn) * 32 + lane]);
                mma_f16(acc[nn], a0, a1, a2, a3, bb.x, bb.y);
            }
        }

        // q tile -> smem. c0,c1 -> row rbase; c2,c3 -> row rbase+8.
#pragma unroll
        for (int nn = 0; nn < 4; ++nn) {
            const int col = 8 * (4 * nh + nn) + 2 * tig;
            *reinterpret_cast<float2*>(q_sm + rbase * QST + col)       = make_float2(acc[nn][0], acc[nn][1]);
            *reinterpret_cast<float2*>(q_sm + (rbase + 8) * QST + col) = make_float2(acc[nn][2], acc[nn][3]);
        }
    }
    __syncthreads();

    // ---- weights: 8 warps scan 4 local q-rows each; lane = col pair ----
    {
        const int r0 = 4 * w;
        float2 p = make_float2(0.f, 0.f);
        if (w > 0) p = *reinterpret_cast<const float2*>(q_sm + (r0 - 1) * QST + 2 * lane);
        for (int r = r0; r < r0 + 4; ++r) {
            float2 v = *reinterpret_cast<const float2*>(q_sm + r * QST + 2 * lane);
            float nn = v.x * v.x + v.y * v.y;
            float cc = v.x * p.x + v.y * p.y;
#pragma unroll
            for (int off = 16; off; off >>= 1) {
                nn += __shfl_xor_sync(0xffffffffu, nn, off);
                cc += __shfl_xor_sync(0xffffffffu, cc, off);
            }
            if (lane == 0) {
                nrm[r] = fmaxf(nn, 1e-5f);
                if (r > 0) crs[r - 1] = cc;
            }
            p = v;
        }
    }
    __syncthreads();

    if (tid < OUTR) {
        const int l = l0 + tid;
        if (l < LDIM) {
            const int sz = __ldg(size + b);
            const int i  = tid;               // nrm/crs index of global row l-1
            float a0 = -1e30f, a2 = -1e30f;
            if (l >= 1 && l < sz)
                a0 = crs[i] / (nrm[i] * nrm[i + 1]);
            int lim2 = sz - 1; if (lim2 < 0) lim2 = 0;
            if (l < lim2)
                a2 = crs[i + 1] / (nrm[i + 1] * nrm[i + 2]);

            float mx = fmaxf(1.0f, fmaxf(a0, a2));
            float e0 = expf(a0 - mx);
            float e1 = expf(1.0f - mx);
            float e2 = expf(a2 - mx);
            float inv = 1.0f / (e0 + e1 + e2);
            wsm[tid] = make_float2(e0 * inv, e2 * inv);
        }
    }
    __syncthreads();

    // ---- combine: register rotation. unit u < 225: j = u%75, chunk = u/75 ----
    // Out-of-range smem rows are zeros and their weights are exactly 0.
    if (tid < 225) {
        const int j   = tid % 75;
        const int ch  = tid / 75;         // 0..2
        const int lr0 = ch * 10;
        const __half* scol = s_h + 4 * j;
        float4* o4 = reinterpret_cast<float4*>(out);

        float4 prev = lds_h4(scol + lr0 * SRS2);         // global row l0+lr0-1
        float4 cur  = lds_h4(scol + (lr0 + 1) * SRS2);

#pragma unroll
        for (int i = 0; i < 10; ++i) {
            const int lr = lr0 + i;
            const int l  = l0 + lr;
            if (l >= LDIM) break;
            const float4 nxt = lds_h4(scol + (lr + 2) * SRS2);

            const float2 ww = wsm[lr];
            const float w0 = ww.x, w2 = ww.y, w1 = 1.0f - w0 - w2;

            float4 r;
            r.x = w1 * cur.x; r.y = w1 * cur.y; r.z = w1 * cur.z; r.w = w1 * cur.w;
            r.x = fmaf(w0, prev.x, r.x); r.y = fmaf(w0, prev.y, r.y);
            r.z = fmaf(w0, prev.z, r.z); r.w = fmaf(w0, prev.w, r.w);
            r.x = fmaf(w2, nxt.x, r.x);  r.y = fmaf(w2, nxt.y, r.y);
            r.z = fmaf(w2, nxt.z, r.z);  r.w = fmaf(w2, nxt.w, r.w);

            __stcs(o4 + ((size_t)l * BDIM + b) * 75 + j, r);
            prev = cur;
            cur  = nxt;
        }
    }
}

// ---------------------------------------------------------------------------
extern "C" void kernel_launch(void* const* d_in, const int* in_sizes, int n_in,
                              void* d_out, int out_size) {
    const float* sentence = nullptr;
    const int*   size_arr = nullptr;
    const float* proj     = nullptr;
    for (int i = 0; i < n_in; ++i) {
        if (in_sizes[i] == LDIM * BDIM * DDIM)      sentence = (const float*)d_in[i];
        else if (in_sizes[i] == DDIM * HDIM)        proj     = (const float*)d_in[i];
        else if (in_sizes[i] == BDIM)               size_arr = (const int*)d_in[i];
    }
    float* out = (float*)d_out;

    const int smem_bytes = ROWS * SRS2 * 2     // S fp16     19968
                         + ROWS * QST * 4      // q tile      8448
                         + 2 * ROWS * 4        // nrm, crs     256
                         + OUTR * 8;           // weights      240
    cudaFuncSetAttribute(k_fused, cudaFuncAttributeMaxDynamicSharedMemorySize,
                         smem_bytes);

    k_packB<<<(KSTEPS * 256 + 255) / 256, 256>>>(proj);
    k_fused<<<BDIM * NSEG, NTHR, smem_bytes>>>(sentence, size_arr, out);
}

// round 12
// speedup vs baseline: 1.2600x; 1.2600x over previous
#include <cuda_runtime.h>
#include <cuda_fp16.h>
#include <cstdint>

// Problem dims
#define LDIM 128
#define BDIM 2048
#define DDIM 300
#define HDIM 60

// Fused-kernel layout: one CTA = one b, one 30-row l-segment
#define KC     32
#define NCH    10
#define SRS2   312         // S smem row stride (halfs); frag banks all distinct
#define QST    66          // q smem row stride (floats)
#define NTHR   256
#define ROWS   32          // smem rows: global l0-1 .. l0+30 (2 m16 tiles)
#define OUTR   30
#define NSEG   5
#define KSTEPS 19          // ceil(300/16)

// Pre-packed B fragments (fp16 pairs), 38.9 KB, L1/L2-resident
__device__ uint2 g_bpackh[KSTEPS * 256];

__device__ __forceinline__ void mma_f16(float* c, uint32_t a0, uint32_t a1,
                                        uint32_t a2, uint32_t a3,
                                        uint32_t b0, uint32_t b1) {
    asm volatile(
        "mma.sync.aligned.m16n8k16.row.col.f32.f16.f16.f32 "
        "{%0,%1,%2,%3}, {%4,%5,%6,%7}, {%8,%9}, {%0,%1,%2,%3};"
        : "+f"(c[0]), "+f"(c[1]), "+f"(c[2]), "+f"(c[3])
        : "r"(a0), "r"(a1), "r"(a2), "r"(a3), "r"(b0), "r"(b1));
}
__device__ __forceinline__ float4 lds_h4(const __half* p) {
    uint2 u = *reinterpret_cast<const uint2*>(p);
    __half2 a = *reinterpret_cast<__half2*>(&u.x);
    __half2 b = *reinterpret_cast<__half2*>(&u.y);
    float2 fa = __half22float2(a), fb = __half22float2(b);
    return make_float4(fa.x, fa.y, fb.x, fb.y);
}

// ---------------------------------------------------------------------------
// Kernel 0 (one-shot, tiny): pack B fragments, fp16.
// ---------------------------------------------------------------------------
__global__ void k_packB(const float* __restrict__ P) {
    const int e = blockIdx.x * 256 + threadIdx.x;
    if (e >= KSTEPS * 256) return;
    const int ks = e >> 8;
    const int n  = (e >> 5) & 7;
    const int ln = e & 31;
    const int tg = ln & 3, g = ln >> 2;
    const int k  = ks * 16 + 2 * tg;
    const int h  = 8 * n + g;
    float v[4] = {0.f, 0.f, 0.f, 0.f};
    if (h < HDIM) {
        if (k     < DDIM) v[0] = P[(size_t)(k)     * HDIM + h];
        if (k + 1 < DDIM) v[1] = P[(size_t)(k + 1) * HDIM + h];
        if (k + 8 < DDIM) v[2] = P[(size_t)(k + 8) * HDIM + h];
        if (k + 9 < DDIM) v[3] = P[(size_t)(k + 9) * HDIM + h];
    }
    __half2 b0 = __floats2half2_rn(v[0], v[1]);
    __half2 b1 = __floats2half2_rn(v[2], v[3]);
    uint2 u;
    u.x = *reinterpret_cast<uint32_t*>(&b0);
    u.y = *reinterpret_cast<uint32_t*>(&b1);
    g_bpackh[e] = u;
}

// ---------------------------------------------------------------------------
// Fused kernel (R10 base): blockIdx -> (b = blk/NSEG, seg), l0 = 30*seg.
//  1) stage S rows (fp16, invalid rows = zeros), one barrier
//  2) MMA m16n8k16 over ALL 8 warps (warp = tile x n-quarter)  [R10 config]
//  3) norms / neighbor-dots / masked softmax
//  4) combine via rotation over ALL 256 threads: 375 units of
//     (col j, 6-long l-chunk); thread takes units tid and tid+256.
//     smem reads 1.33x/elem (was 3x), chain depth 6.
// Smem 28.9 KB -> 5 CTAs/SM.
// ---------------------------------------------------------------------------
__global__ __launch_bounds__(NTHR, 5) void k_fused(const float* __restrict__ S,
                                                   const int* __restrict__ size,
                                                   float* __restrict__ out) {
    extern __shared__ char smraw[];
    __half* s_h  = reinterpret_cast<__half*>(smraw);                   // [ROWS][SRS2]
    float*  q_sm = reinterpret_cast<float*>(smraw + ROWS * SRS2 * 2);  // [ROWS][QST]
    float*  nrm  = q_sm + ROWS * QST;                                  // [ROWS]
    float*  crs  = nrm + ROWS;                                         // [ROWS]
    float2* wsm  = reinterpret_cast<float2*>(crs + ROWS);              // [OUTR]
    const uint32_t* sh32 = reinterpret_cast<const uint32_t*>(s_h);

    const int tid  = threadIdx.x;
    const int w    = tid >> 5;
    const int lane = tid & 31;
    const int g    = lane >> 2;
    const int tig  = lane & 3;
    const int blk  = blockIdx.x;
    const int b    = blk / NSEG;
    const int l0   = (blk - b * NSEG) * OUTR;

    // ---- stage all S rows: thread = (row = tid>>3, kq4 = tid&7) ----
    {
        const int row  = tid >> 3;
        const int kq4  = tid & 7;
        const int grow = l0 - 1 + row;
        const bool gv  = (grow >= 0 && grow < LDIM);
        const float* base = S + ((size_t)(gv ? grow : 0) * BDIM + b) * DDIM;
        __half* drow = s_h + row * SRS2;
#pragma unroll
        for (int c = 0; c < NCH; ++c) {
            const int k0 = c * KC + kq4 * 4;
            if (k0 >= SRS2) break;
            float4 v = make_float4(0.f, 0.f, 0.f, 0.f);
            if (gv && k0 + 4 <= DDIM) v = *reinterpret_cast<const float4*>(base + k0);
            __half2 h01 = __floats2half2_rn(v.x, v.y);
            __half2 h23 = __floats2half2_rn(v.z, v.w);
            uint2 u;
            u.x = *reinterpret_cast<uint32_t*>(&h01);
            u.y = *reinterpret_cast<uint32_t*>(&h23);
            *reinterpret_cast<uint2*>(drow + k0) = u;
        }
    }
    __syncthreads();

    // ---- MMA: all 8 warps; warp = (tile t = w>>2, n-quarter nq = w&3) ----
    {
        float acc[2][4];
#pragma unroll
        for (int n = 0; n < 2; ++n)
#pragma unroll
            for (int i = 0; i < 4; ++i) acc[n][i] = 0.f;

        const int t     = w >> 2;
        const int nq    = w & 3;
        const int rbase = 16 * t + g;

#pragma unroll
        for (int ks = 0; ks < KSTEPS; ++ks) {
            const int base0 = rbase * 156 + ks * 8 + tig;   // u32 view, stride 156
            const uint32_t a0 = sh32[base0];
            const uint32_t a1 = sh32[base0 + 8 * 156];
            const uint32_t a2 = sh32[base0 + 4];
            const uint32_t a3 = sh32[base0 + 8 * 156 + 4];
#pragma unroll
            for (int nn = 0; nn < 2; ++nn) {
                const uint2 bb = __ldg(&g_bpackh[(ks * 8 + 2 * nq + nn) * 32 + lane]);
                mma_f16(acc[nn], a0, a1, a2, a3, bb.x, bb.y);
            }
        }

        // q tile -> smem. c0,c1 -> row rbase; c2,c3 -> row rbase+8.
#pragma unroll
        for (int nn = 0; nn < 2; ++nn) {
            const int col = 8 * (2 * nq + nn) + 2 * tig;
            *reinterpret_cast<float2*>(q_sm + rbase * QST + col)       = make_float2(acc[nn][0], acc[nn][1]);
            *reinterpret_cast<float2*>(q_sm + (rbase + 8) * QST + col) = make_float2(acc[nn][2], acc[nn][3]);
        }
    }
    __syncthreads();

    // ---- weights: 8 warps scan 4 local q-rows each; lane = col pair ----
    {
        const int r0 = 4 * w;
        float2 p = make_float2(0.f, 0.f);
        if (w > 0) p = *reinterpret_cast<const float2*>(q_sm + (r0 - 1) * QST + 2 * lane);
        for (int r = r0; r < r0 + 4; ++r) {
            float2 v = *reinterpret_cast<const float2*>(q_sm + r * QST + 2 * lane);
            float nn = v.x * v.x + v.y * v.y;
            float cc = v.x * p.x + v.y * p.y;
#pragma unroll
            for (int off = 16; off; off >>= 1) {
                nn += __shfl_xor_sync(0xffffffffu, nn, off);
                cc += __shfl_xor_sync(0xffffffffu, cc, off);
            }
            if (lane == 0) {
                nrm[r] = fmaxf(nn, 1e-5f);
                if (r > 0) crs[r - 1] = cc;
            }
            p = v;
        }
    }
    __syncthreads();

    if (tid < OUTR) {
        const int l = l0 + tid;
        if (l < LDIM) {
            const int sz = __ldg(size + b);
            const int i  = tid;               // nrm/crs index of global row l-1
            float a0 = -1e30f, a2 = -1e30f;
            if (l >= 1 && l < sz)
                a0 = crs[i] / (nrm[i] * nrm[i + 1]);
            int lim2 = sz - 1; if (lim2 < 0) lim2 = 0;
            if (l < lim2)
                a2 = crs[i + 1] / (nrm[i + 1] * nrm[i + 2]);

            float mx = fmaxf(1.0f, fmaxf(a0, a2));
            float e0 = expf(a0 - mx);
            float e1 = expf(1.0f - mx);
            float e2 = expf(a2 - mx);
            float inv = 1.0f / (e0 + e1 + e2);
            wsm[tid] = make_float2(e0 * inv, e2 * inv);
        }
    }
    __syncthreads();

    // ---- combine: rotation, ALL threads. 375 units = 75 cols x 5 chunks of 6.
    // Thread handles units tid and tid+256. Out-of-range smem rows are zeros;
    // break precedes any wsm read for l >= 128.
    {
        float4* o4 = reinterpret_cast<float4*>(out);
#pragma unroll
        for (int pass = 0; pass < 2; ++pass) {
            const int u = tid + pass * NTHR;
            if (u >= 375) break;
            const int ch  = u / 75;          // 0..4
            const int j   = u - ch * 75;
            const int lr0 = ch * 6;
            if (l0 + lr0 >= LDIM) continue;
            const __half* scol = s_h + 4 * j;

            float4 prev = lds_h4(scol + lr0 * SRS2);        // global row l0+lr0-1
            float4 cur  = lds_h4(scol + (lr0 + 1) * SRS2);

#pragma unroll
            for (int i = 0; i < 6; ++i) {
                const int lr = lr0 + i;
                const int l  = l0 + lr;
                if (l >= LDIM) break;
                const float4 nxt = lds_h4(scol + (lr + 2) * SRS2);

                const float2 ww = wsm[lr];
                const float w0 = ww.x, w2 = ww.y, w1 = 1.0f - w0 - w2;

                float4 r;
                r.x = w1 * cur.x; r.y = w1 * cur.y; r.z = w1 * cur.z; r.w = w1 * cur.w;
                r.x = fmaf(w0, prev.x, r.x); r.y = fmaf(w0, prev.y, r.y);
                r.z = fmaf(w0, prev.z, r.z); r.w = fmaf(w0, prev.w, r.w);
                r.x = fmaf(w2, nxt.x, r.x);  r.y = fmaf(w2, nxt.y, r.y);
                r.z = fmaf(w2, nxt.z, r.z);  r.w = fmaf(w2, nxt.w, r.w);

                __stcs(o4 + ((size_t)l * BDIM + b) * 75 + j, r);
                prev = cur;
                cur  = nxt;
            }
        }
    }
}

// ---------------------------------------------------------------------------
extern "C" void kernel_launch(void* const* d_in, const int* in_sizes, int n_in,
                              void* d_out, int out_size) {
    const float* sentence = nullptr;
    const int*   size_arr = nullptr;
    const float* proj     = nullptr;
    for (int i = 0; i < n_in; ++i) {
        if (in_sizes[i] == LDIM * BDIM * DDIM)      sentence = (const float*)d_in[i];
        else if (in_sizes[i] == DDIM * HDIM)        proj     = (const float*)d_in[i];
        else if (in_sizes[i] == BDIM)               size_arr = (const int*)d_in[i];
    }
    float* out = (float*)d_out;

    const int smem_bytes = ROWS * SRS2 * 2     // S fp16     19968
                         + ROWS * QST * 4      // q tile      8448
                         + 2 * ROWS * 4        // nrm, crs     256
                         + OUTR * 8;           // weights      240
    cudaFuncSetAttribute(k_fused, cudaFuncAttributeMaxDynamicSharedMemorySize,
                         smem_bytes);

    k_packB<<<(KSTEPS * 256 + 255) / 256, 256>>>(proj);
    k_fused<<<BDIM * NSEG, NTHR, smem_bytes>>>(sentence, size_arr, out);
}